// round 10
// baseline (speedup 1.0000x reference)
#include <cuda_runtime.h>
#include <cuda_fp16.h>

// Problem constants (shapes fixed by the reference)
#define N_MAX 100000
#define E_MAX 1600000

// Scratch (allocation-free rule: __device__ globals)
__device__ __align__(16) __half2 g_msg[E_MAX * 4];     // normalized edge messages, fp16 (25.6 MB)
__device__ __align__(16) __half2 g_AC[N_MAX * 8];      // row-role node projection, fp16 (3.2 MB)
__device__ __align__(16) __half2 g_BD[N_MAX * 8];      // col-role node projection, fp16 (3.2 MB)
// Parity-split fp16 accumulators (reduce fp16 running-sum rounding ~sqrt(2)).
__device__ __align__(16) __half2 g_Sm[2][N_MAX * 4];   // Sum of m over incoming edges
__device__ __align__(16) __half2 g_S2a[2][N_MAX * 4];  // Sum of h0[row]*m  (k = 0)
__device__ __align__(16) __half2 g_S2b[2][N_MAX * 4];  // Sum of h1[row]*m  (k = 1)

__device__ __forceinline__ unsigned h2_bits(__half2 h) {
    return *reinterpret_cast<unsigned*>(&h);
}
__device__ __forceinline__ __half2 bits_h2(unsigned u) {
    return *reinterpret_cast<__half2*>(&u);
}

// 8B vector reduction: 4 fp16 accumulators in one transaction (sm_90+).
__device__ __forceinline__ void red_add_v2_f16x2(__half2* p, __half2 a, __half2 b) {
    asm volatile("red.global.add.noftz.v2.f16x2 [%0], {%1, %2};"
                 :: "l"(p), "r"(h2_bits(a)), "r"(h2_bits(b))
                 : "memory");
}

// ---------------------------------------------------------------------------
// Kernel 1: per-node prep (unchanged).
// ---------------------------------------------------------------------------
__global__ void prep_kernel(const float* __restrict__ stat,
                            const float* __restrict__ dyn,
                            const float* __restrict__ We1,
                            const float* __restrict__ Wf0,
                            float* __restrict__ h, int N) {
    __shared__ float sW[32 * 16 + 64];  // We1 rows 0..31, then W_filter[0] (8x8)
    for (int i = threadIdx.x; i < 32 * 16; i += blockDim.x) sW[i] = We1[i];
    for (int i = threadIdx.x; i < 64; i += blockDim.x) sW[512 + i] = Wf0[i];
    __syncthreads();

    int n = blockIdx.x * blockDim.x + threadIdx.x;
    if (n >= N) return;

    float s[8], d[8];
    {
        const float4* sp = (const float4*)stat + n * 2;
        float4 t0 = sp[0], t1 = sp[1];
        s[0] = t0.x; s[1] = t0.y; s[2] = t0.z; s[3] = t0.w;
        s[4] = t1.x; s[5] = t1.y; s[6] = t1.z; s[7] = t1.w;
        const float4* dp = (const float4*)dyn + n * 2;
        float4 u0 = dp[0], u1 = dp[1];
        d[0] = u0.x; d[1] = u0.y; d[2] = u0.z; d[3] = u0.w;
        d[4] = u1.x; d[5] = u1.y; d[6] = u1.z; d[7] = u1.w;
    }

    float ac[16], bd[16];
#pragma unroll
    for (int j = 0; j < 16; j++) { ac[j] = 0.f; bd[j] = 0.f; }
#pragma unroll
    for (int i = 0; i < 8; i++) {
        float si = s[i], di = d[i];
#pragma unroll
        for (int j = 0; j < 16; j++) {
            ac[j] += si * sW[i * 16 + j];
            ac[j] += di * sW[(16 + i) * 16 + j];
            bd[j] += si * sW[(8 + i) * 16 + j];
            bd[j] += di * sW[(24 + i) * 16 + j];
        }
    }

    {
        uint4* acp = (uint4*)(g_AC + n * 8);
        uint4* bdp = (uint4*)(g_BD + n * 8);
        __half2 a[8], b[8];
#pragma unroll
        for (int q = 0; q < 8; q++) {
            a[q] = __floats2half2_rn(ac[q * 2], ac[q * 2 + 1]);
            b[q] = __floats2half2_rn(bd[q * 2], bd[q * 2 + 1]);
        }
        acp[0] = make_uint4(h2_bits(a[0]), h2_bits(a[1]), h2_bits(a[2]), h2_bits(a[3]));
        acp[1] = make_uint4(h2_bits(a[4]), h2_bits(a[5]), h2_bits(a[6]), h2_bits(a[7]));
        bdp[0] = make_uint4(h2_bits(b[0]), h2_bits(b[1]), h2_bits(b[2]), h2_bits(b[3]));
        bdp[1] = make_uint4(h2_bits(b[4]), h2_bits(b[5]), h2_bits(b[6]), h2_bits(b[7]));
    }

    // h0 = dyn @ W_filter[0]
    float h0[8];
#pragma unroll
    for (int j = 0; j < 8; j++) h0[j] = 0.f;
#pragma unroll
    for (int i = 0; i < 8; i++) {
        float di = d[i];
#pragma unroll
        for (int j = 0; j < 8; j++) h0[j] += di * sW[512 + i * 8 + j];
    }
    float4* hp = (float4*)h + n * 2;
    hp[0] = make_float4(h0[0], h0[1], h0[2], h0[3]);
    hp[1] = make_float4(h0[4], h0[5], h0[6], h0[7]);

    uint4 z = make_uint4(0u, 0u, 0u, 0u);
    ((uint4*)(g_Sm[0]  + n * 4))[0] = z;
    ((uint4*)(g_Sm[1]  + n * 4))[0] = z;
    ((uint4*)(g_S2a[0] + n * 4))[0] = z;
    ((uint4*)(g_S2a[1] + n * 4))[0] = z;
    ((uint4*)(g_S2b[0] + n * 4))[0] = z;
    ((uint4*)(g_S2b[1] + n * 4))[0] = z;
}

// ---------------------------------------------------------------------------
// Kernel 2: per-edge, 2 THREADS PER EDGE (lanes 2t, 2t+1 split the edge).
// Each thread gathers only 16B halves of AC/BD/h -> ~2x fewer L1tex
// wavefronts on the random gathers. One shfl exchange for the j-split matmul.
// ---------------------------------------------------------------------------
__global__ void edge0_kernel(const int* __restrict__ eidx,
                             const float* __restrict__ ef,
                             const float* __restrict__ We1,
                             const float* __restrict__ be1,
                             const float* __restrict__ We2,
                             const float* __restrict__ be2,
                             const float* __restrict__ h, int E) {
    __shared__ float sWeE[64];   // We1 rows 32..35 ([4][16])
    __shared__ float sbe1[16];
    __shared__ float sWe2[128];  // [16][8]
    __shared__ float sbe2[8];
    for (int i = threadIdx.x; i < 64; i += blockDim.x) sWeE[i] = We1[512 + i];
    for (int i = threadIdx.x; i < 16; i += blockDim.x) sbe1[i] = be1[i];
    for (int i = threadIdx.x; i < 128; i += blockDim.x) sWe2[i] = We2[i];
    for (int i = threadIdx.x; i < 8; i += blockDim.x) sbe2[i] = be2[i];
    __syncthreads();

    int t = blockIdx.x * blockDim.x + threadIdx.x;
    int e = t >> 1;
    int q = t & 1;          // which half of the edge this thread owns
    if (e >= E) return;

    int row = eidx[e];
    int col = eidx[E + e];
    int p = e & 1;

    // 16B half-gathers (one LDG.128 each)
    uint4 pa = ((const uint4*)(g_AC + row * 8))[q];   // hidden j in [8q, 8q+8)
    uint4 pb = ((const uint4*)(g_BD + col * 8))[q];
    float4 hq = ((const float4*)h)[row * 2 + q];      // h0 d in [4q, 4q+4)
    float2 efh = ((const float2*)ef)[e * 2 + q];      // my 2 of 4 edge features

    unsigned amask = __activemask();
    // exchange ef halves so both threads have all 4
    float eo0 = __shfl_xor_sync(amask, efh.x, 1);
    float eo1 = __shfl_xor_sync(amask, efh.y, 1);
    float ef0 = q ? eo0 : efh.x;
    float ef1 = q ? eo1 : efh.y;
    float ef2 = q ? efh.x : eo0;
    float ef3 = q ? efh.y : eo1;

    // hidden (my j-half): AC+BD (fp16 add) + be1 + ef @ WeE, then ReLU
    int jb = 8 * q;
    float hv[8];
    {
        unsigned aw[4] = {pa.x, pa.y, pa.z, pa.w};
        unsigned bw[4] = {pb.x, pb.y, pb.z, pb.w};
#pragma unroll
        for (int u = 0; u < 4; u++) {
            float2 f = __half22float2(__hadd2(bits_h2(aw[u]), bits_h2(bw[u])));
            int j0 = jb + 2 * u, j1 = j0 + 1;
            float v0 = f.x + sbe1[j0] + ef0 * sWeE[j0] + ef1 * sWeE[16 + j0]
                       + ef2 * sWeE[32 + j0] + ef3 * sWeE[48 + j0];
            float v1 = f.y + sbe1[j1] + ef0 * sWeE[j1] + ef1 * sWeE[16 + j1]
                       + ef2 * sWeE[32 + j1] + ef3 * sWeE[48 + j1];
            hv[2 * u + 0] = fmaxf(v0, 0.f);
            hv[2 * u + 1] = fmaxf(v1, 0.f);
        }
    }

    // partial m over my j-half (bias added by q==0 only), then pair-exchange
    float m[8];
#pragma unroll
    for (int d = 0; d < 8; d++) m[d] = q ? 0.f : sbe2[d];
#pragma unroll
    for (int jl = 0; jl < 8; jl++) {
        float hj = hv[jl];
        const float* wrow = &sWe2[(jb + jl) * 8];
#pragma unroll
        for (int d = 0; d < 8; d++) m[d] += hj * wrow[d];
    }
#pragma unroll
    for (int d = 0; d < 8; d++) m[d] += __shfl_xor_sync(amask, m[d], 1);

    // normalize (both threads hold identical full m)
    float ss = 0.f;
#pragma unroll
    for (int d = 0; d < 8; d++) ss += m[d] * m[d];
    float inv = (ss > 0.f) ? rsqrtf(ss) : 0.f;
#pragma unroll
    for (int d = 0; d < 8; d++) m[d] *= inv;

    // my d-half: store msg (8B) + REDs (8B each)
    int db = 4 * q;
    __half2 p0 = __floats2half2_rn(m[db + 0], m[db + 1]);
    __half2 p1 = __floats2half2_rn(m[db + 2], m[db + 3]);
    ((uint2*)(g_msg + e * 4 + q * 2))[0] = make_uint2(h2_bits(p0), h2_bits(p1));

    red_add_v2_f16x2(g_Sm[p] + col * 4 + q * 2, p0, p1);

    __half2 s0 = __floats2half2_rn(hq.x * m[db + 0], hq.y * m[db + 1]);
    __half2 s1 = __floats2half2_rn(hq.z * m[db + 2], hq.w * m[db + 3]);
    red_add_v2_f16x2(g_S2a[p] + col * 4 + q * 2, s0, s1);
}

// ---------------------------------------------------------------------------
// Kernel 3: per-edge k=1 pass, 2 THREADS PER EDGE. No shuffles needed.
// ---------------------------------------------------------------------------
__global__ void flux_kernel(const int* __restrict__ eidx,
                            const float* __restrict__ h, int E) {
    int t = blockIdx.x * blockDim.x + threadIdx.x;
    int e = t >> 1;
    int q = t & 1;
    if (e >= E) return;

    int row = eidx[e];
    int col = eidx[E + e];
    int p = e & 1;

    uint2 pk = ((const uint2*)(g_msg + e * 4 + q * 2))[0];   // my m d-half
    float4 hq = ((const float4*)h)[row * 2 + q];             // h1 d-half

    float2 m0 = __half22float2(bits_h2(pk.x));
    float2 m1 = __half22float2(bits_h2(pk.y));

    __half2 s0 = __floats2half2_rn(hq.x * m0.x, hq.y * m0.y);
    __half2 s1 = __floats2half2_rn(hq.z * m1.x, hq.w * m1.y);
    red_add_v2_f16x2(g_S2b[p] + col * 4 + q * 2, s0, s1);
}

// ---------------------------------------------------------------------------
// Kernel 4: agg[n] = h[n]*Sm[n] - S2[n];  h += agg @ W_filter[k+1].
// ---------------------------------------------------------------------------
__global__ void update_kernel(const float* __restrict__ Wk,
                              float* __restrict__ h, int N, int which_s2) {
    __shared__ float sW[64];
    if (threadIdx.x < 64) sW[threadIdx.x] = Wk[threadIdx.x];
    __syncthreads();

    int n = blockIdx.x * blockDim.x + threadIdx.x;
    if (n >= N) return;

    const __half2* s2base0 = which_s2 ? g_S2b[0] : g_S2a[0];
    const __half2* s2base1 = which_s2 ? g_S2b[1] : g_S2a[1];

    uint4 sm0 = ((const uint4*)(g_Sm[0] + n * 4))[0];
    uint4 sm1 = ((const uint4*)(g_Sm[1] + n * 4))[0];
    uint4 sa0 = ((const uint4*)(s2base0 + n * 4))[0];
    uint4 sa1 = ((const uint4*)(s2base1 + n * 4))[0];

    float sm[8], s2[8];
    {
        const unsigned* w0 = &sm0.x;
        const unsigned* w1 = &sm1.x;
        const unsigned* v0 = &sa0.x;
        const unsigned* v1 = &sa1.x;
#pragma unroll
        for (int qq = 0; qq < 4; qq++) {
            float2 fa0 = __half22float2(bits_h2(w0[qq]));
            float2 fa1 = __half22float2(bits_h2(w1[qq]));
            float2 fb0 = __half22float2(bits_h2(v0[qq]));
            float2 fb1 = __half22float2(bits_h2(v1[qq]));
            sm[qq * 2 + 0] = fa0.x + fa1.x;
            sm[qq * 2 + 1] = fa0.y + fa1.y;
            s2[qq * 2 + 0] = fb0.x + fb1.x;
            s2[qq * 2 + 1] = fb0.y + fb1.y;
        }
    }

    float4* hp = (float4*)h + n * 2;
    float4 h0 = hp[0], h1 = hp[1];
    float hv[8] = {h0.x, h0.y, h0.z, h0.w, h1.x, h1.y, h1.z, h1.w};

    float a[8];
#pragma unroll
    for (int j = 0; j < 8; j++) a[j] = hv[j] * sm[j] - s2[j];

    float o[8] = {hv[0], hv[1], hv[2], hv[3], hv[4], hv[5], hv[6], hv[7]};
#pragma unroll
    for (int i = 0; i < 8; i++) {
        float ai = a[i];
#pragma unroll
        for (int j = 0; j < 8; j++) o[j] += ai * sW[i * 8 + j];
    }
    hp[0] = make_float4(o[0], o[1], o[2], o[3]);
    hp[1] = make_float4(o[4], o[5], o[6], o[7]);
}

// ---------------------------------------------------------------------------
extern "C" void kernel_launch(void* const* d_in, const int* in_sizes, int n_in,
                              void* d_out, int out_size) {
    const float* stat = (const float*)d_in[0];   // [N, 8]
    const float* dyn  = (const float*)d_in[1];   // [N, 8]
    const int*   eidx = (const int*)d_in[2];     // [2, E]
    const float* ef   = (const float*)d_in[3];   // [E, 4]
    const float* Wf   = (const float*)d_in[4];   // [3, 8, 8]
    const float* We1  = (const float*)d_in[5];   // [36, 16]
    const float* be1  = (const float*)d_in[6];   // [16]
    const float* We2  = (const float*)d_in[7];   // [16, 8]
    const float* be2  = (const float*)d_in[8];   // [8]

    float* h = (float*)d_out;                    // [N, 8] — used as live h buffer

    int N = in_sizes[1] / 8;
    int E = in_sizes[2] / 2;
    if (N > N_MAX) N = N_MAX;
    if (E > E_MAX) E = E_MAX;

    int nb = (N + 255) / 256;
    int eb2 = (2 * E + 255) / 256;   // 2 threads per edge

    prep_kernel<<<nb, 256>>>(stat, dyn, We1, Wf, h, N);
    edge0_kernel<<<eb2, 256>>>(eidx, ef, We1, be1, We2, be2, h, E);
    update_kernel<<<nb, 256>>>(Wf + 64, h, N, 0);   // h1 = h0 + (h0*Sm - S2a)@W1
    flux_kernel<<<eb2, 256>>>(eidx, h, E);
    update_kernel<<<nb, 256>>>(Wf + 128, h, N, 1);  // h2 = h1 + (h1*Sm - S2b)@W2
}

// round 12
// speedup vs baseline: 1.0428x; 1.0428x over previous
#include <cuda_runtime.h>
#include <cuda_fp16.h>

// Problem constants (shapes fixed by the reference)
#define N_MAX 100000
#define E_MAX 1600000

typedef unsigned long long ull;

// Scratch (allocation-free rule: __device__ globals)
__device__ __align__(16) __half2 g_msg[E_MAX * 4];     // normalized edge messages, fp16 (25.6 MB)
__device__ __align__(16) __half2 g_AC[N_MAX * 8];      // row-role node projection, fp16 (3.2 MB)
__device__ __align__(16) __half2 g_BD[N_MAX * 8];      // col-role node projection, fp16 (3.2 MB)
// Parity-split fp16 accumulators (reduce fp16 running-sum rounding ~sqrt(2)).
__device__ __align__(16) __half2 g_Sm[2][N_MAX * 4];   // Sum of m over incoming edges
__device__ __align__(16) __half2 g_S2a[2][N_MAX * 4];  // Sum of h0[row]*m  (k = 0)
__device__ __align__(16) __half2 g_S2b[2][N_MAX * 4];  // Sum of h1[row]*m  (k = 1)

__device__ __forceinline__ unsigned h2_bits(__half2 h) {
    return *reinterpret_cast<unsigned*>(&h);
}
__device__ __forceinline__ __half2 bits_h2(unsigned u) {
    return *reinterpret_cast<__half2*>(&u);
}

// One 16B vector reduction carrying 8 fp16 accumulators (sm_90+).
__device__ __forceinline__ void red_add_v4_f16x2(__half2* p,
                                                 __half2 a, __half2 b,
                                                 __half2 c, __half2 d) {
    asm volatile("red.global.add.noftz.v4.f16x2 [%0], {%1, %2, %3, %4};"
                 :: "l"(p), "r"(h2_bits(a)), "r"(h2_bits(b)),
                    "r"(h2_bits(c)), "r"(h2_bits(d))
                 : "memory");
}

// Packed f32x2 ops (Blackwell sm_100+, PTX ISA 8.6) — 2 fp32 lanes per instr.
#define F32X2_FMA(out, a, b, c) \
    asm("fma.rn.f32x2 %0, %1, %2, %3;" : "=l"(out) : "l"(a), "l"(b), "l"(c))
#define F32X2_ADD(out, a, b) \
    asm("add.rn.f32x2 %0, %1, %2;" : "=l"(out) : "l"(a), "l"(b))
#define PACKF2(out, lo, hi) \
    asm("mov.b64 %0, {%1, %2};" : "=l"(out) : "f"(lo), "f"(hi))
#define UNPACKF2(lo, hi, in) \
    asm("mov.b64 {%0, %1}, %2;" : "=f"(lo), "=f"(hi) : "l"(in))

// L2 eviction-priority via createpolicy + cache_hint (works on sm_100 ptxas;
// the inline .L2::evict_* qualifiers are v8-only there).
__device__ __forceinline__ ull mk_policy_evict_first() {
    ull p;
    asm("createpolicy.fractional.L2::evict_first.b64 %0, 1.0;" : "=l"(p));
    return p;
}
__device__ __forceinline__ ull mk_policy_evict_last() {
    ull p;
    asm("createpolicy.fractional.L2::evict_last.b64 %0, 1.0;" : "=l"(p));
    return p;
}
__device__ __forceinline__ float4 ldg_f4_hint(const float4* p, ull pol) {
    float4 v;
    asm("ld.global.nc.L2::cache_hint.v4.f32 {%0, %1, %2, %3}, [%4], %5;"
        : "=f"(v.x), "=f"(v.y), "=f"(v.z), "=f"(v.w) : "l"(p), "l"(pol));
    return v;
}
__device__ __forceinline__ uint4 ldg_u4_hint(const uint4* p, ull pol) {
    uint4 v;
    asm("ld.global.nc.L2::cache_hint.v4.b32 {%0, %1, %2, %3}, [%4], %5;"
        : "=r"(v.x), "=r"(v.y), "=r"(v.z), "=r"(v.w) : "l"(p), "l"(pol));
    return v;
}
__device__ __forceinline__ int ldg_i_hint(const int* p, ull pol) {
    int v;
    asm("ld.global.nc.L2::cache_hint.b32 %0, [%1], %2;" : "=r"(v) : "l"(p), "l"(pol));
    return v;
}
__device__ __forceinline__ void stg_u4_hint(uint4* p, uint4 v, ull pol) {
    asm volatile("st.global.L2::cache_hint.v4.b32 [%0], {%1, %2, %3, %4}, %5;"
                 :: "l"(p), "r"(v.x), "r"(v.y), "r"(v.z), "r"(v.w), "l"(pol)
                 : "memory");
}

// ---------------------------------------------------------------------------
// Kernel 1: per-node prep.
// ---------------------------------------------------------------------------
__global__ void prep_kernel(const float* __restrict__ stat,
                            const float* __restrict__ dyn,
                            const float* __restrict__ We1,
                            const float* __restrict__ Wf0,
                            float* __restrict__ h, int N) {
    __shared__ float sW[32 * 16 + 64];  // We1 rows 0..31, then W_filter[0] (8x8)
    for (int i = threadIdx.x; i < 32 * 16; i += blockDim.x) sW[i] = We1[i];
    for (int i = threadIdx.x; i < 64; i += blockDim.x) sW[512 + i] = Wf0[i];
    __syncthreads();

    int n = blockIdx.x * blockDim.x + threadIdx.x;
    if (n >= N) return;

    float s[8], d[8];
    {
        const float4* sp = (const float4*)stat + n * 2;
        float4 t0 = sp[0], t1 = sp[1];
        s[0] = t0.x; s[1] = t0.y; s[2] = t0.z; s[3] = t0.w;
        s[4] = t1.x; s[5] = t1.y; s[6] = t1.z; s[7] = t1.w;
        const float4* dp = (const float4*)dyn + n * 2;
        float4 u0 = dp[0], u1 = dp[1];
        d[0] = u0.x; d[1] = u0.y; d[2] = u0.z; d[3] = u0.w;
        d[4] = u1.x; d[5] = u1.y; d[6] = u1.z; d[7] = u1.w;
    }

    float ac[16], bd[16];
#pragma unroll
    for (int j = 0; j < 16; j++) { ac[j] = 0.f; bd[j] = 0.f; }
#pragma unroll
    for (int i = 0; i < 8; i++) {
        float si = s[i], di = d[i];
#pragma unroll
        for (int j = 0; j < 16; j++) {
            ac[j] += si * sW[i * 16 + j];
            ac[j] += di * sW[(16 + i) * 16 + j];
            bd[j] += si * sW[(8 + i) * 16 + j];
            bd[j] += di * sW[(24 + i) * 16 + j];
        }
    }

    // pack to fp16: 16 halfs = 2 x 16B stores per array
    {
        uint4* acp = (uint4*)(g_AC + n * 8);
        uint4* bdp = (uint4*)(g_BD + n * 8);
        __half2 a[8], b[8];
#pragma unroll
        for (int q = 0; q < 8; q++) {
            a[q] = __floats2half2_rn(ac[q * 2], ac[q * 2 + 1]);
            b[q] = __floats2half2_rn(bd[q * 2], bd[q * 2 + 1]);
        }
        acp[0] = make_uint4(h2_bits(a[0]), h2_bits(a[1]), h2_bits(a[2]), h2_bits(a[3]));
        acp[1] = make_uint4(h2_bits(a[4]), h2_bits(a[5]), h2_bits(a[6]), h2_bits(a[7]));
        bdp[0] = make_uint4(h2_bits(b[0]), h2_bits(b[1]), h2_bits(b[2]), h2_bits(b[3]));
        bdp[1] = make_uint4(h2_bits(b[4]), h2_bits(b[5]), h2_bits(b[6]), h2_bits(b[7]));
    }

    // h0 = dyn @ W_filter[0]
    float h0[8];
#pragma unroll
    for (int j = 0; j < 8; j++) h0[j] = 0.f;
#pragma unroll
    for (int i = 0; i < 8; i++) {
        float di = d[i];
#pragma unroll
        for (int j = 0; j < 8; j++) h0[j] += di * sW[512 + i * 8 + j];
    }
    float4* hp = (float4*)h + n * 2;
    hp[0] = make_float4(h0[0], h0[1], h0[2], h0[3]);
    hp[1] = make_float4(h0[4], h0[5], h0[6], h0[7]);

    uint4 z = make_uint4(0u, 0u, 0u, 0u);
    ((uint4*)(g_Sm[0]  + n * 4))[0] = z;
    ((uint4*)(g_Sm[1]  + n * 4))[0] = z;
    ((uint4*)(g_S2a[0] + n * 4))[0] = z;
    ((uint4*)(g_S2a[1] + n * 4))[0] = z;
    ((uint4*)(g_S2b[0] + n * 4))[0] = z;
    ((uint4*)(g_S2b[1] + n * 4))[0] = z;
}

// ---------------------------------------------------------------------------
// Kernel 2: per-edge — MLP (packed f32x2), normalize, store msg (fp16,
// evict_last), accumulate Sm[col] += m and S2a[col] += h0[row]*m.
// ef read evict_first (read-once); eidx read + msg store evict_last
// (both re-read by flux).
// ---------------------------------------------------------------------------
__global__ void edge0_kernel(const int* __restrict__ eidx,
                             const float* __restrict__ ef,
                             const float* __restrict__ We1,
                             const float* __restrict__ be1,
                             const float* __restrict__ We2,
                             const float* __restrict__ be2,
                             const float* __restrict__ h, int E) {
    __shared__ __align__(16) float sWeE[64];   // We1 rows 32..35 ([4][16])
    __shared__ __align__(16) float sbe1[16];
    __shared__ __align__(16) float sWe2[128];  // [16][8]
    __shared__ __align__(16) float sbe2[8];
    for (int i = threadIdx.x; i < 64; i += blockDim.x) sWeE[i] = We1[512 + i];
    for (int i = threadIdx.x; i < 16; i += blockDim.x) sbe1[i] = be1[i];
    for (int i = threadIdx.x; i < 128; i += blockDim.x) sWe2[i] = We2[i];
    for (int i = threadIdx.x; i < 8; i += blockDim.x) sbe2[i] = be2[i];
    __syncthreads();

    int e = blockIdx.x * blockDim.x + threadIdx.x;
    if (e >= E) return;

    ull pol_first = mk_policy_evict_first();
    ull pol_last  = mk_policy_evict_last();

    int row = ldg_i_hint(eidx + e, pol_last);
    int col = ldg_i_hint(eidx + E + e, pol_last);
    int p = e & 1;

    // front-batch the gathers: AC[row] (32B), BD[col] (32B), h0[row], ef
    const uint4* acp = (const uint4*)(g_AC + row * 8);
    const uint4* bdp = (const uint4*)(g_BD + col * 8);
    uint4 pa0 = acp[0], pa1 = acp[1];
    uint4 pb0 = bdp[0], pb1 = bdp[1];
    const float4* hr = (const float4*)h + row * 2;
    float4 r0 = hr[0], r1 = hr[1];
    float4 efv = ldg_f4_hint((const float4*)ef + e, pol_first);

    // hid2[q] = f32x2 pair (2q, 2q+1) of: AC[row] + BD[col] + be1
    ull hid2[8];
    {
        unsigned aw[8] = {pa0.x, pa0.y, pa0.z, pa0.w, pa1.x, pa1.y, pa1.z, pa1.w};
        unsigned bw[8] = {pb0.x, pb0.y, pb0.z, pb0.w, pb1.x, pb1.y, pb1.z, pb1.w};
#pragma unroll
        for (int q = 0; q < 8; q++) {
            __half2 hs = __hadd2(bits_h2(aw[q]), bits_h2(bw[q]));
            float2 f = __half22float2(hs);
            ull t; PACKF2(t, f.x, f.y);
            F32X2_ADD(hid2[q], t, *(const ull*)&sbe1[2 * q]);
        }
    }

    // hid2 += ef @ We1[32:36]  (pairs along j; 32 packed FMAs)
    {
        ull e0, e1, e2, e3;
        PACKF2(e0, efv.x, efv.x);
        PACKF2(e1, efv.y, efv.y);
        PACKF2(e2, efv.z, efv.z);
        PACKF2(e3, efv.w, efv.w);
#pragma unroll
        for (int q = 0; q < 8; q++) {
            F32X2_FMA(hid2[q], e0, *(const ull*)&sWeE[2 * q],      hid2[q]);
            F32X2_FMA(hid2[q], e1, *(const ull*)&sWeE[16 + 2 * q], hid2[q]);
            F32X2_FMA(hid2[q], e2, *(const ull*)&sWeE[32 + 2 * q], hid2[q]);
            F32X2_FMA(hid2[q], e3, *(const ull*)&sWeE[48 + 2 * q], hid2[q]);
        }
    }

    // ReLU (scalar), then m = hidden @ We2 + be2 with d-pairs packed (64 FMAs)
    float hv[16];
#pragma unroll
    for (int q = 0; q < 8; q++) {
        float lo, hi;
        UNPACKF2(lo, hi, hid2[q]);
        hv[2 * q + 0] = fmaxf(lo, 0.f);
        hv[2 * q + 1] = fmaxf(hi, 0.f);
    }
    ull acc[4];
#pragma unroll
    for (int q = 0; q < 4; q++) acc[q] = *(const ull*)&sbe2[2 * q];
#pragma unroll
    for (int j = 0; j < 16; j++) {
        ull hjj; PACKF2(hjj, hv[j], hv[j]);
#pragma unroll
        for (int q = 0; q < 4; q++)
            F32X2_FMA(acc[q], hjj, *(const ull*)&sWe2[j * 8 + 2 * q], acc[q]);
    }
    float m[8];
#pragma unroll
    for (int q = 0; q < 4; q++) UNPACKF2(m[2 * q], m[2 * q + 1], acc[q]);

    // normalize (0 when norm == 0)
    float ss = 0.f;
#pragma unroll
    for (int d = 0; d < 8; d++) ss += m[d] * m[d];
    float inv = (ss > 0.f) ? rsqrtf(ss) : 0.f;
#pragma unroll
    for (int d = 0; d < 8; d++) m[d] *= inv;

    // pack msg to fp16; store once (evict_last — flux re-reads it)
    __half2 p0 = __floats2half2_rn(m[0], m[1]);
    __half2 p1 = __floats2half2_rn(m[2], m[3]);
    __half2 p2 = __floats2half2_rn(m[4], m[5]);
    __half2 p3 = __floats2half2_rn(m[6], m[7]);
    stg_u4_hint((uint4*)(g_msg + e * 4),
                make_uint4(h2_bits(p0), h2_bits(p1), h2_bits(p2), h2_bits(p3)),
                pol_last);

    // Sm[col] += m
    red_add_v4_f16x2(g_Sm[p] + col * 4, p0, p1, p2, p3);

    // S2a[col] += h0[row] * m
    __half2 s0 = __floats2half2_rn(r0.x * m[0], r0.y * m[1]);
    __half2 s1 = __floats2half2_rn(r0.z * m[2], r0.w * m[3]);
    __half2 s2 = __floats2half2_rn(r1.x * m[4], r1.y * m[5]);
    __half2 s3 = __floats2half2_rn(r1.z * m[6], r1.w * m[7]);
    red_add_v4_f16x2(g_S2a[p] + col * 4, s0, s1, s2, s3);
}

// ---------------------------------------------------------------------------
// Kernel 3: per-edge pass for k = 1:  S2b[col] += h1[row] * m.
// msg read evict_first (last consumer).
// ---------------------------------------------------------------------------
__global__ void flux_kernel(const int* __restrict__ eidx,
                            const float* __restrict__ h, int E) {
    int e = blockIdx.x * blockDim.x + threadIdx.x;
    if (e >= E) return;

    ull pol_first = mk_policy_evict_first();

    int row = eidx[e];
    int col = eidx[E + e];
    int p = e & 1;

    uint4 pk = ldg_u4_hint((const uint4*)(g_msg + e * 4), pol_first);
    const float4* hr = (const float4*)h + row * 2;
    float4 r0 = hr[0], r1 = hr[1];

    float2 m0 = __half22float2(bits_h2(pk.x));
    float2 m1 = __half22float2(bits_h2(pk.y));
    float2 m2 = __half22float2(bits_h2(pk.z));
    float2 m3 = __half22float2(bits_h2(pk.w));

    __half2 s0 = __floats2half2_rn(r0.x * m0.x, r0.y * m0.y);
    __half2 s1 = __floats2half2_rn(r0.z * m1.x, r0.w * m1.y);
    __half2 s2 = __floats2half2_rn(r1.x * m2.x, r1.y * m2.y);
    __half2 s3 = __floats2half2_rn(r1.z * m3.x, r1.w * m3.y);
    red_add_v4_f16x2(g_S2b[p] + col * 4, s0, s1, s2, s3);
}

// ---------------------------------------------------------------------------
// Kernel 4: agg[n] = h[n]*Sm[n] - S2[n];  h += agg @ W_filter[k+1].
// which_s2: 0 -> S2a (k=0), 1 -> S2b (k=1).
// ---------------------------------------------------------------------------
__global__ void update_kernel(const float* __restrict__ Wk,
                              float* __restrict__ h, int N, int which_s2) {
    __shared__ float sW[64];
    if (threadIdx.x < 64) sW[threadIdx.x] = Wk[threadIdx.x];
    __syncthreads();

    int n = blockIdx.x * blockDim.x + threadIdx.x;
    if (n >= N) return;

    const __half2* s2base0 = which_s2 ? g_S2b[0] : g_S2a[0];
    const __half2* s2base1 = which_s2 ? g_S2b[1] : g_S2a[1];

    uint4 sm0 = ((const uint4*)(g_Sm[0] + n * 4))[0];
    uint4 sm1 = ((const uint4*)(g_Sm[1] + n * 4))[0];
    uint4 sa0 = ((const uint4*)(s2base0 + n * 4))[0];
    uint4 sa1 = ((const uint4*)(s2base1 + n * 4))[0];

    float sm[8], s2[8];
    {
        const unsigned* w0 = &sm0.x;
        const unsigned* w1 = &sm1.x;
        const unsigned* v0 = &sa0.x;
        const unsigned* v1 = &sa1.x;
#pragma unroll
        for (int q = 0; q < 4; q++) {
            float2 fa0 = __half22float2(bits_h2(w0[q]));
            float2 fa1 = __half22float2(bits_h2(w1[q]));
            float2 fb0 = __half22float2(bits_h2(v0[q]));
            float2 fb1 = __half22float2(bits_h2(v1[q]));
            sm[q * 2 + 0] = fa0.x + fa1.x;
            sm[q * 2 + 1] = fa0.y + fa1.y;
            s2[q * 2 + 0] = fb0.x + fb1.x;
            s2[q * 2 + 1] = fb0.y + fb1.y;
        }
    }

    float4* hp = (float4*)h + n * 2;
    float4 h0 = hp[0], h1 = hp[1];
    float hv[8] = {h0.x, h0.y, h0.z, h0.w, h1.x, h1.y, h1.z, h1.w};

    float a[8];
#pragma unroll
    for (int j = 0; j < 8; j++) a[j] = hv[j] * sm[j] - s2[j];

    float o[8] = {hv[0], hv[1], hv[2], hv[3], hv[4], hv[5], hv[6], hv[7]};
#pragma unroll
    for (int i = 0; i < 8; i++) {
        float ai = a[i];
#pragma unroll
        for (int j = 0; j < 8; j++) o[j] += ai * sW[i * 8 + j];
    }
    hp[0] = make_float4(o[0], o[1], o[2], o[3]);
    hp[1] = make_float4(o[4], o[5], o[6], o[7]);
}

// ---------------------------------------------------------------------------
extern "C" void kernel_launch(void* const* d_in, const int* in_sizes, int n_in,
                              void* d_out, int out_size) {
    const float* stat = (const float*)d_in[0];   // [N, 8]
    const float* dyn  = (const float*)d_in[1];   // [N, 8]
    const int*   eidx = (const int*)d_in[2];     // [2, E]
    const float* ef   = (const float*)d_in[3];   // [E, 4]
    const float* Wf   = (const float*)d_in[4];   // [3, 8, 8]
    const float* We1  = (const float*)d_in[5];   // [36, 16]
    const float* be1  = (const float*)d_in[6];   // [16]
    const float* We2  = (const float*)d_in[7];   // [16, 8]
    const float* be2  = (const float*)d_in[8];   // [8]

    float* h = (float*)d_out;                    // [N, 8] — used as live h buffer

    int N = in_sizes[1] / 8;
    int E = in_sizes[2] / 2;
    if (N > N_MAX) N = N_MAX;
    if (E > E_MAX) E = E_MAX;

    int nb = (N + 255) / 256;
    int eb = (E + 255) / 256;

    prep_kernel<<<nb, 256>>>(stat, dyn, We1, Wf, h, N);
    edge0_kernel<<<eb, 256>>>(eidx, ef, We1, be1, We2, be2, h, E);
    update_kernel<<<nb, 256>>>(Wf + 64, h, N, 0);   // h1 = h0 + (h0*Sm - S2a)@W1
    flux_kernel<<<eb, 256>>>(eidx, h, E);
    update_kernel<<<nb, 256>>>(Wf + 128, h, N, 1);  // h2 = h1 + (h1*Sm - S2b)@W2
}